// round 14
// baseline (speedup 1.0000x reference)
#include <cuda_runtime.h>
#include <cuda_fp16.h>
#include <cstdint>

#define DIMS 64
#define SVOL (64*64*64)
#define NBATCH 4
#define NCLASS 4
#define NPAIR 12
#define NVOL 24
#define NTOT (NBATCH*SVOL)
#define SMOOTHV 1e-5f
#define GRID_BLOCKS 592
#define K12_UNITS 256
#define K3_UNITS 768            // 12 pairs * 64 h

__device__ __half g_F2h[(size_t)NVOL * SVOL];    // pass-2 2D SQUARED distances (fp16)
__device__ __half g_probh[(size_t)NPAIR * SVOL]; // probs classes 1..3 (fp16)
__device__ float g_TP[16];      // zero at load; reset by last block each call
__device__ float g_PS[16];
__device__ float g_CNT[16];
__device__ float g_focal;
__device__ float g_bsum[NPAIR];
__device__ volatile unsigned g_bdone[NBATCH];
__device__ unsigned g_k12cnt;
__device__ unsigned g_k3cnt;
__device__ unsigned g_fin;

__device__ __forceinline__ float sqrt_ap(float x) {
    float y; asm("sqrt.approx.f32 %0, %1;" : "=f"(y) : "f"(x)); return y;
}

__device__ __forceinline__ float ndist(unsigned long long M, int i) {
    if (M == 0ULL) return __int_as_float(0x7f800000);   // +inf
    unsigned long long L = M << (63 - i);
    int dl = L ? __clzll((long long)L) : 9999;
    unsigned long long R = M >> i;
    int dr = R ? (__ffsll((long long)R) - 1) : 9999;
    return (float)min(dl, dr);
}

// ============================================================
// Windowed exact 1D DT over 8 rows x 2 adjacent columns (half2).
// SQ=false: input is distance f; SQ=true: input already squared.
// Results <= 16 provably exact; else exact fp32 full-scan fallback.
// ============================================================
template<int HSTRIDE, bool SQ>
__device__ __forceinline__ void dt8v(const __half* __restrict__ base, int c, float2 acc[8]) {
    const __half2* b2 = reinterpret_cast<const __half2*>(base);
    const int S2 = HSTRIDE / 2;
    const __half2 inf2 = __halves2half2(__ushort_as_half(0x7C00), __ushort_as_half(0x7C00));
    __half2 s[14];
#pragma unroll
    for (int mi = 0; mi < 14; mi++) {
        int j = c - 3 + mi;
        if (j >= 0 && j < 64) {
            __half2 v = b2[(size_t)j * S2];
            s[mi] = SQ ? v : __hmul2(v, v);
        } else s[mi] = inf2;
    }
    const __half2 c1 = __float2half2_rn(1.f);
    const __half2 c4 = __float2half2_rn(4.f);
    const __half2 c9 = __float2half2_rn(9.f);
    __half2 a2[8];
#pragma unroll
    for (int t = 0; t < 8; t++) {
        __half2 a = s[t + 3];
        a = __hmin2(a, __hadd2(s[t + 2], c1)); a = __hmin2(a, __hadd2(s[t + 4], c1));
        a = __hmin2(a, __hadd2(s[t + 1], c4)); a = __hmin2(a, __hadd2(s[t + 5], c4));
        a = __hmin2(a, __hadd2(s[t + 0], c9)); a = __hmin2(a, __hadd2(s[t + 6], c9));
        a2[t] = a;
    }
    __half2 mx2 = a2[0];
#pragma unroll
    for (int t = 1; t < 8; t++) mx2 = __hmax2(mx2, a2[t]);
#pragma unroll
    for (int t = 0; t < 8; t++) acc[t] = __half22float2(a2[t]);
    const float fmx = fmaxf(__low2float(mx2), __high2float(mx2));
    if (__any_sync(0xFFFFFFFFu, fmx > 16.0f)) {
        float jf = 0.f;
        for (int j = 0; j < 64; j++, jf += 1.0f) {
            const float f0 = __half2float(base[(size_t)j * HSTRIDE]);
            const float f1 = __half2float(base[(size_t)j * HSTRIDE + 1]);
            const float q0 = SQ ? f0 : f0 * f0;
            const float q1 = SQ ? f1 : f1 * f1;
#pragma unroll
            for (int t = 0; t < 8; t++) {
                const float dk = (float)(c + t) - jf;
                const float d2 = dk * dk;
                acc[t].x = fminf(acc[t].x, d2 + q0);
                acc[t].y = fminf(acc[t].y, d2 + q1);
            }
        }
    }
}

// ============================================================
// Single persistent kernel, 256-thread blocks, 4/SM.
// K12 slices and K3 units both work-stolen (batch-major).
// Last-finished block assembles the loss and resets all state.
// ============================================================
__global__ void __launch_bounds__(256, 4) k_all(const float* __restrict__ preds,
                                                const int* __restrict__ tgt32,
                                                float* __restrict__ out) {
    extern __shared__ __half T[];            // 6 * 4096 halves = 48 KB
    __shared__ unsigned sball[3][64][2];
    __shared__ float red13[12 * 8];
    __shared__ float red[8];
    __shared__ int sany;
    __shared__ unsigned su;
    __shared__ unsigned sfin;
    const int tid = threadIdx.x;
    const unsigned full = 0xFFFFFFFFu;
    const int wid = tid >> 5;

    // ---------- int64 detection: warp 0 checks 64 odd words ----------
    if (tid < 32) {
        const int v = tgt32[2 * tid + 1] | tgt32[2 * (tid + 32) + 1];
        const unsigned bal = __ballot_sync(full, v != 0);
        if (tid == 0) sany = (int)bal;
    }
    __syncthreads();
    const int f64 = (sany == 0) ? 1 : 0;

    // ================= K12: work-stolen slices =================
    for (;;) {
        if (tid == 0) su = atomicAdd(&g_k12cnt, 1u);
        __syncthreads();
        const unsigned u12 = su;
        if (u12 >= K12_UNITS) break;
        const int b = (int)(u12 >> 6);
        const int d = (int)(u12 & 63);

        float a9[9];
#pragma unroll
        for (int q = 0; q < 9; q++) a9[q] = 0.f;
        int cn1 = 0, cn2 = 0, cn3 = 0;

        // ---------- Phase A: 16 iterations of 256 threads ----------
#pragma unroll 4
        for (int r = 0; r < 16; r++) {
            const int sl = tid + r * 256;
            const int s = d * 4096 + sl;
            const int gidx = b * SVOL + s;
            const int t = tgt32[f64 ? (gidx << 1) : gidx];

            const float x0 = preds[(size_t)(b * 4 + 0) * SVOL + s];
            const float x1 = preds[(size_t)(b * 4 + 1) * SVOL + s];
            const float x2 = preds[(size_t)(b * 4 + 2) * SVOL + s];
            const float x3 = preds[(size_t)(b * 4 + 3) * SVOL + s];

            const float m  = fmaxf(fmaxf(x0, x1), fmaxf(x2, x3));
            const float e0 = __expf(x0 - m), e1 = __expf(x1 - m);
            const float e2 = __expf(x2 - m), e3 = __expf(x3 - m);
            const float se = e0 + e1 + e2 + e3;
            const float inv = __fdividef(1.0f, se);
            const float p0 = e0 * inv, p1 = e1 * inv, p2 = e2 * inv, p3 = e3 * inv;

            const float xt = (t == 0) ? x0 : (t == 1) ? x1 : (t == 2) ? x2 : x3;
            const float ce = -(xt - m - __logf(se));
            const float pt = (t == 0) ? p0 : (t == 1) ? p1 : (t == 2) ? p2 : p3;
            const float om = 1.0f - pt;

            g_probh[(size_t)(b * 3 + 0) * SVOL + s] = __float2half(p1);
            g_probh[(size_t)(b * 3 + 1) * SVOL + s] = __float2half(p2);
            g_probh[(size_t)(b * 3 + 2) * SVOL + s] = __float2half(p3);

            a9[0] += (t == 0) ? p0 : 0.f;
            a9[1] += (t == 1) ? p1 : 0.f;
            a9[2] += (t == 2) ? p2 : 0.f;
            a9[3] += (t == 3) ? p3 : 0.f;
            a9[4] += p0; a9[5] += p1; a9[6] += p2; a9[7] += p3;
            a9[8] += om * om * ce;

            const unsigned bal1 = __ballot_sync(full, t == 1);
            const unsigned bal2 = __ballot_sync(full, t == 2);
            const unsigned bal3 = __ballot_sync(full, t == 3);
            cn1 += __popc(bal1); cn2 += __popc(bal2); cn3 += __popc(bal3);
            if ((tid & 31) == 0) {
                const int h = r * 4 + (wid >> 1);
                const int hf = wid & 1;
                sball[0][h][hf] = bal1;
                sball[1][h][hf] = bal2;
                sball[2][h][hf] = bal3;
            }
        }
        __syncthreads();

        // ---------- Phase B: pass-1 line distances into SMEM ----------
        {
            const int h = tid >> 2;
            const int w0 = (tid & 3) * 16;
#pragma unroll
            for (int cm = 0; cm < 3; cm++) {
                const unsigned long long M = (unsigned long long)sball[cm][h][0] |
                                             ((unsigned long long)sball[cm][h][1] << 32);
                const unsigned long long Mn = ~M;
                __half* t0 = T + (cm * 2 + 0) * 4096 + h * 64;
                __half* t1 = T + (cm * 2 + 1) * 4096 + h * 64;
#pragma unroll
                for (int q = 0; q < 16; q++) {
                    const int w = w0 + q;
                    t0[w] = __float2half(ndist(M, w));
                    t1[w] = __float2half(ndist(Mn, w));
                }
            }
        }
        __syncthreads();

        // ---------- Phase C: H-pass, SMEM -> g_F2h (store d^2) ----------
        {
            const int w2 = (tid & 31) * 2;
            const int c = (tid >> 5) * 8;
#pragma unroll
            for (int vol = 0; vol < 6; vol++) {
                const __half* base = T + vol * 4096 + w2;
                float2 acc[8];
                dt8v<64, false>(base, c, acc);
                __half* dst = g_F2h + (size_t)(b * 6 + vol) * SVOL + (size_t)d * 4096 +
                              (size_t)c * 64 + w2;
#pragma unroll
                for (int t = 0; t < 8; t++) {
                    __half2 o = __halves2half2(__float2half(acc[t].x),
                                               __float2half(acc[t].y));
                    *reinterpret_cast<__half2*>(dst + (size_t)t * 64) = o;
                }
            }
        }

        // ---------- Phase D: 12-quantity block reduce ----------
#pragma unroll
        for (int q = 0; q < 9; q++) {
            float v = a9[q];
#pragma unroll
            for (int o = 16; o > 0; o >>= 1) v += __shfl_down_sync(full, v, o);
            if ((tid & 31) == 0) red13[q * 8 + wid] = v;
        }
        if ((tid & 31) == 0) {
            red13[9 * 8 + wid]  = (float)cn1;
            red13[10 * 8 + wid] = (float)cn2;
            red13[11 * 8 + wid] = (float)cn3;
        }
        __syncthreads();
        if (tid < 12) {
            float sum = 0.f;
#pragma unroll
            for (int k = 0; k < 8; k++) sum += red13[tid * 8 + k];
            if (tid < 4)       atomicAdd(&g_TP[b * 4 + tid], sum);
            else if (tid < 8)  atomicAdd(&g_PS[b * 4 + tid - 4], sum);
            else if (tid == 8) atomicAdd(&g_focal, sum);
            else {
                atomicAdd(&g_CNT[b * 4 + tid - 8], sum);
                atomicAdd(&g_CNT[b * 4], -sum);     // CNT0 = 4096 - c1 - c2 - c3
            }
        }
        if (tid == 12) atomicAdd(&g_CNT[b * 4], 4096.0f);

        // ---- release this slice ----
        __threadfence();
        __syncthreads();
        if (tid == 0) atomicAdd((unsigned*)&g_bdone[b], 1u);
    }

    // ================= K3: work-stolen D-pass units =================
    for (;;) {
        if (tid == 0) su = atomicAdd(&g_k3cnt, 1u);
        __syncthreads();
        const unsigned u = su;
        if (u >= K3_UNITS) break;
        const int p = u >> 6;                        // 0..11 (batch-major)
        const int pb = p / 3;
        const int h = u & 63;
        const int w2 = (tid & 31) * 2;
        const int c = (tid >> 5) * 8;

        if (tid == 0) {                              // acquire batch pb
            while (g_bdone[pb] < 64u) __nanosleep(64);
        }
        __syncthreads();
        __threadfence();

        const __half* baseO = g_F2h + (size_t)(2 * p) * SVOL + (size_t)h * 64 + w2;
        const __half* baseI = baseO + SVOL;

        float2 ao[8], ai[8];
        dt8v<4096, true>(baseO, c, ao);
        dt8v<4096, true>(baseI, c, ai);

        const __half* pp = g_probh + (size_t)p * SVOL + (size_t)c * 4096 + (size_t)h * 64 + w2;
        float local = 0.f;
#pragma unroll
        for (int t = 0; t < 8; t++) {
            const float2 pr = __half22float2(*reinterpret_cast<const __half2*>(pp + (size_t)t * 4096));
            const float s0 = sqrt_ap(ao[t].x) - sqrt_ap(ai[t].x);
            const float s1 = sqrt_ap(ao[t].y) - sqrt_ap(ai[t].y);
            local = fmaf(s0, pr.x, local);
            local = fmaf(s1, pr.y, local);
        }
#pragma unroll
        for (int o = 16; o > 0; o >>= 1) local += __shfl_down_sync(0xFFFFFFFFu, local, o);
        if ((tid & 31) == 0) red[tid >> 5] = local;
        __syncthreads();
        if (tid == 0) {
            float sum = 0.f;
#pragma unroll
            for (int k = 0; k < 8; k++) sum += red[k];
            atomicAdd(&g_bsum[p], sum);
        }
        __syncthreads();
    }

    // ================= finalization by last-finished block =================
    if (tid == 0) {
        __threadfence();
        sfin = atomicAdd(&g_fin, 1u);
    }
    __syncthreads();
    if (sfin == GRID_BLOCKS - 1 && tid < 32) {
        __threadfence();
        float dterm = 0.f;
        if (tid < 16) {
            const float TP = g_TP[tid], PS = g_PS[tid], CNT = g_CNT[tid];
            const float FP = PS - TP;
            const float FN = CNT - TP;
            dterm = (TP + SMOOTHV) / (TP + 0.3f * FP + 0.7f * FN + SMOOTHV);
        }
        float bterm = 0.f;
        if (tid < NPAIR) {
            const int bb = tid / 3, cc = tid % 3 + 1;
            const float cnt = g_CNT[bb * 4 + cc];
            if (cnt > 0.f) {
                if (cnt >= (float)SVOL)
                    bterm = -g_PS[bb * 4 + cc] / (float)SVOL;   // sdf == -1 everywhere
                else
                    bterm = g_bsum[tid] / (float)SVOL;
            }
        }
        const float foc = g_focal;
#pragma unroll
        for (int o = 16; o > 0; o >>= 1) {
            dterm += __shfl_down_sync(0xFFFFFFFFu, dterm, o);
            bterm += __shfl_down_sync(0xFFFFFFFFu, bterm, o);
        }
        if (tid == 0) {
            const float l_dice = 1.0f - dterm / 16.0f;
            const float l_main = foc / (float)NTOT;
            const float l_bound = bterm / (12.0f + 1e-8f);
            out[0] = l_dice + l_main + 0.01f * l_bound;
        }
        // reset all state for next graph replay
        if (tid < 16) { g_TP[tid] = 0.f; g_PS[tid] = 0.f; g_CNT[tid] = 0.f; }
        if (tid < NPAIR) g_bsum[tid] = 0.f;
        if (tid < NBATCH) g_bdone[tid] = 0u;
        if (tid == 0) { g_focal = 0.f; g_k12cnt = 0u; g_k3cnt = 0u; g_fin = 0u; }
    }
}

extern "C" void kernel_launch(void* const* d_in, const int* in_sizes, int n_in,
                              void* d_out, int out_size) {
    const float* preds = (const float*)d_in[0];
    const int*   tgt   = (const int*)d_in[1];
    (void)in_sizes; (void)n_in; (void)out_size;

    const int smem = 6 * 4096 * (int)sizeof(__half);   // 48 KB dynamic
    cudaFuncSetAttribute(k_all, cudaFuncAttributeMaxDynamicSharedMemorySize, smem);

    k_all<<<GRID_BLOCKS, 256, smem>>>(preds, tgt, (float*)d_out);
}

// round 15
// speedup vs baseline: 1.4735x; 1.4735x over previous
#include <cuda_runtime.h>
#include <cuda_fp16.h>
#include <cstdint>

#define DIMS 64
#define SVOL (64*64*64)
#define NBATCH 4
#define NCLASS 4
#define NPAIR 12
#define NVOL 24
#define NTOT (NBATCH*SVOL)
#define SMOOTHV 1e-5f
#define K12_BLOCKS 256
#define K12_UNITS 256
#define K3_UNITS 384            // 12 pairs * 32 (h-pairs)

__device__ __half g_F2h[(size_t)NVOL * SVOL];    // pass-2 2D SQUARED distances (fp16)
__device__ __half g_probh[(size_t)NPAIR * SVOL]; // probs classes 1..3 (fp16)
__device__ float g_TP[16];      // zero at load; reset by last block each call
__device__ float g_PS[16];
__device__ float g_CNT[16];
__device__ float g_focal;
__device__ float g_bsum[NPAIR];
__device__ volatile unsigned g_bdone[NBATCH];
__device__ unsigned g_k12cnt;
__device__ unsigned g_k3cnt;
__device__ unsigned g_fin;

__device__ __forceinline__ float sqrt_ap(float x) {
    float y; asm("sqrt.approx.f32 %0, %1;" : "=f"(y) : "f"(x)); return y;
}
__device__ __forceinline__ void cp_async16(uint32_t dst, const __half* src) {
    asm volatile("cp.async.cg.shared.global [%0], [%1], 16;" :: "r"(dst), "l"(src));
}

__device__ __forceinline__ float ndist(unsigned long long M, int i) {
    if (M == 0ULL) return __int_as_float(0x7f800000);   // +inf
    unsigned long long L = M << (63 - i);
    int dl = L ? __clzll((long long)L) : 9999;
    unsigned long long R = M >> i;
    int dr = R ? (__ffsll((long long)R) - 1) : 9999;
    return (float)min(dl, dr);
}

// ============================================================
// Windowed exact 1D DT over 8 rows x 2 adjacent columns (half2).
// SQ=false: input is distance f; SQ=true: input already squared.
// Results <= 16 provably exact; else exact fp32 full-scan fallback.
// ============================================================
template<int HSTRIDE, bool SQ>
__device__ __forceinline__ void dt8v(const __half* __restrict__ base, int c, float2 acc[8]) {
    const __half2* b2 = reinterpret_cast<const __half2*>(base);
    const int S2 = HSTRIDE / 2;
    const __half2 inf2 = __halves2half2(__ushort_as_half(0x7C00), __ushort_as_half(0x7C00));
    __half2 s[14];
#pragma unroll
    for (int mi = 0; mi < 14; mi++) {
        int j = c - 3 + mi;
        if (j >= 0 && j < 64) {
            __half2 v = b2[(size_t)j * S2];
            s[mi] = SQ ? v : __hmul2(v, v);
        } else s[mi] = inf2;
    }
    const __half2 c1 = __float2half2_rn(1.f);
    const __half2 c4 = __float2half2_rn(4.f);
    const __half2 c9 = __float2half2_rn(9.f);
    __half2 a2[8];
#pragma unroll
    for (int t = 0; t < 8; t++) {
        __half2 a = s[t + 3];
        a = __hmin2(a, __hadd2(s[t + 2], c1)); a = __hmin2(a, __hadd2(s[t + 4], c1));
        a = __hmin2(a, __hadd2(s[t + 1], c4)); a = __hmin2(a, __hadd2(s[t + 5], c4));
        a = __hmin2(a, __hadd2(s[t + 0], c9)); a = __hmin2(a, __hadd2(s[t + 6], c9));
        a2[t] = a;
    }
    __half2 mx2 = a2[0];
#pragma unroll
    for (int t = 1; t < 8; t++) mx2 = __hmax2(mx2, a2[t]);
#pragma unroll
    for (int t = 0; t < 8; t++) acc[t] = __half22float2(a2[t]);
    const float fmx = fmaxf(__low2float(mx2), __high2float(mx2));
    if (__any_sync(0xFFFFFFFFu, fmx > 16.0f)) {
        float jf = 0.f;
        for (int j = 0; j < 64; j++, jf += 1.0f) {
            const float f0 = __half2float(base[(size_t)j * HSTRIDE]);
            const float f1 = __half2float(base[(size_t)j * HSTRIDE + 1]);
            const float q0 = SQ ? f0 : f0 * f0;
            const float q1 = SQ ? f1 : f1 * f1;
#pragma unroll
            for (int t = 0; t < 8; t++) {
                const float dk = (float)(c + t) - jf;
                const float d2 = dk * dk;
                acc[t].x = fminf(acc[t].x, d2 + q0);
                acc[t].y = fminf(acc[t].y, d2 + q1);
            }
        }
    }
}

// ============================================================
// Single persistent kernel, 512 threads, 2 blocks/SM.
// K12 slices and K3 units both work-stolen (batch-major).
// K3 stages its 6 tiles (O, I, prob x 2 h-slices) via cp.async
// into the 48KB SMEM buffer, then runs the window DT from LDS.
// Last-finished block assembles the loss and resets all state.
// ============================================================
__global__ void __launch_bounds__(512, 2) k_all(const float* __restrict__ preds,
                                                const int* __restrict__ tgt32,
                                                float* __restrict__ out) {
    extern __shared__ __half T[];            // 6 * 4096 halves = 48 KB
    __shared__ unsigned sball[3][64][2];
    __shared__ float red13[12 * 16];
    __shared__ float red[16];
    __shared__ int sany;
    __shared__ unsigned su;
    __shared__ unsigned sfin;
    const int tid = threadIdx.x;
    const unsigned full = 0xFFFFFFFFu;
    const int wid = tid >> 5;

    // ---------- int64 detection: warp 0 checks 64 odd words ----------
    if (tid < 32) {
        const int v = tgt32[2 * tid + 1] | tgt32[2 * (tid + 32) + 1];
        const unsigned bal = __ballot_sync(full, v != 0);
        if (tid == 0) sany = (int)bal;
    }
    __syncthreads();
    const int f64 = (sany == 0) ? 1 : 0;

    // ================= K12: work-stolen slices =================
    for (;;) {
        if (tid == 0) su = atomicAdd(&g_k12cnt, 1u);
        __syncthreads();
        const unsigned u12 = su;
        if (u12 >= K12_UNITS) break;
        const int b = (int)(u12 >> 6);
        const int d = (int)(u12 & 63);

        float a9[9];
#pragma unroll
        for (int q = 0; q < 9; q++) a9[q] = 0.f;
        int cn1 = 0, cn2 = 0, cn3 = 0;

        // ---------- Phase A ----------
#pragma unroll
        for (int r = 0; r < 8; r++) {
            const int sl = tid + r * 512;
            const int s = d * 4096 + sl;
            const int gidx = b * SVOL + s;
            const int t = tgt32[f64 ? (gidx << 1) : gidx];

            const float x0 = preds[(size_t)(b * 4 + 0) * SVOL + s];
            const float x1 = preds[(size_t)(b * 4 + 1) * SVOL + s];
            const float x2 = preds[(size_t)(b * 4 + 2) * SVOL + s];
            const float x3 = preds[(size_t)(b * 4 + 3) * SVOL + s];

            const float m  = fmaxf(fmaxf(x0, x1), fmaxf(x2, x3));
            const float e0 = __expf(x0 - m), e1 = __expf(x1 - m);
            const float e2 = __expf(x2 - m), e3 = __expf(x3 - m);
            const float se = e0 + e1 + e2 + e3;
            const float inv = __fdividef(1.0f, se);
            const float p0 = e0 * inv, p1 = e1 * inv, p2 = e2 * inv, p3 = e3 * inv;

            const float xt = (t == 0) ? x0 : (t == 1) ? x1 : (t == 2) ? x2 : x3;
            const float ce = -(xt - m - __logf(se));
            const float pt = (t == 0) ? p0 : (t == 1) ? p1 : (t == 2) ? p2 : p3;
            const float om = 1.0f - pt;

            g_probh[(size_t)(b * 3 + 0) * SVOL + s] = __float2half(p1);
            g_probh[(size_t)(b * 3 + 1) * SVOL + s] = __float2half(p2);
            g_probh[(size_t)(b * 3 + 2) * SVOL + s] = __float2half(p3);

            a9[0] += (t == 0) ? p0 : 0.f;
            a9[1] += (t == 1) ? p1 : 0.f;
            a9[2] += (t == 2) ? p2 : 0.f;
            a9[3] += (t == 3) ? p3 : 0.f;
            a9[4] += p0; a9[5] += p1; a9[6] += p2; a9[7] += p3;
            a9[8] += om * om * ce;

            const unsigned bal1 = __ballot_sync(full, t == 1);
            const unsigned bal2 = __ballot_sync(full, t == 2);
            const unsigned bal3 = __ballot_sync(full, t == 3);
            cn1 += __popc(bal1); cn2 += __popc(bal2); cn3 += __popc(bal3);
            if ((tid & 31) == 0) {
                const int h = r * 8 + (wid >> 1);
                const int hf = wid & 1;
                sball[0][h][hf] = bal1;
                sball[1][h][hf] = bal2;
                sball[2][h][hf] = bal3;
            }
        }
        __syncthreads();

        // ---------- Phase B: pass-1 line distances into SMEM ----------
        {
            const int h = tid >> 3;
            const int w0 = (tid & 7) * 8;
#pragma unroll
            for (int cm = 0; cm < 3; cm++) {
                const unsigned long long M = (unsigned long long)sball[cm][h][0] |
                                             ((unsigned long long)sball[cm][h][1] << 32);
                const unsigned long long Mn = ~M;
                __half* t0 = T + (cm * 2 + 0) * 4096 + h * 64;
                __half* t1 = T + (cm * 2 + 1) * 4096 + h * 64;
#pragma unroll
                for (int q = 0; q < 8; q++) {
                    const int w = w0 + q;
                    t0[w] = __float2half(ndist(M, w));
                    t1[w] = __float2half(ndist(Mn, w));
                }
            }
        }
        __syncthreads();

        // ---------- Phase C: H-pass, SMEM -> g_F2h (store d^2) ----------
        {
            const int w2 = (tid & 31) * 2;
            const int c = ((tid >> 5) & 7) * 8;
            const int vh = tid >> 8;             // 0..1
#pragma unroll
            for (int vi = 0; vi < 3; vi++) {
                const int vol = vh * 3 + vi;
                const __half* base = T + vol * 4096 + w2;
                float2 acc[8];
                dt8v<64, false>(base, c, acc);
                __half* dst = g_F2h + (size_t)(b * 6 + vol) * SVOL + (size_t)d * 4096 +
                              (size_t)c * 64 + w2;
#pragma unroll
                for (int t = 0; t < 8; t++) {
                    __half2 o = __halves2half2(__float2half(acc[t].x),
                                               __float2half(acc[t].y));
                    *reinterpret_cast<__half2*>(dst + (size_t)t * 64) = o;
                }
            }
        }

        // ---------- Phase D: 12-quantity block reduce ----------
#pragma unroll
        for (int q = 0; q < 9; q++) {
            float v = a9[q];
#pragma unroll
            for (int o = 16; o > 0; o >>= 1) v += __shfl_down_sync(full, v, o);
            if ((tid & 31) == 0) red13[q * 16 + wid] = v;
        }
        if ((tid & 31) == 0) {
            red13[9 * 16 + wid]  = (float)cn1;
            red13[10 * 16 + wid] = (float)cn2;
            red13[11 * 16 + wid] = (float)cn3;
        }
        __syncthreads();
        if (tid < 12) {
            float sum = 0.f;
#pragma unroll
            for (int k = 0; k < 16; k++) sum += red13[tid * 16 + k];
            if (tid < 4)       atomicAdd(&g_TP[b * 4 + tid], sum);
            else if (tid < 8)  atomicAdd(&g_PS[b * 4 + tid - 4], sum);
            else if (tid == 8) atomicAdd(&g_focal, sum);
            else {
                atomicAdd(&g_CNT[b * 4 + tid - 8], sum);
                atomicAdd(&g_CNT[b * 4], -sum);     // CNT0 = 4096 - c1 - c2 - c3
            }
        }
        if (tid == 12) atomicAdd(&g_CNT[b * 4], 4096.0f);

        // ---- release this slice ----
        __threadfence();
        __syncthreads();
        if (tid == 0) atomicAdd((unsigned*)&g_bdone[b], 1u);
    }

    // ================= K3: work-stolen, SMEM-staged D-pass =================
    const uint32_t Tb = (uint32_t)__cvta_generic_to_shared(T);
    for (;;) {
        if (tid == 0) su = atomicAdd(&g_k3cnt, 1u);
        __syncthreads();                    // su visible; prior T reads done
        const unsigned u = su;
        if (u >= K3_UNITS) break;
        const int p = u >> 5;                        // 0..11 (batch-major)
        const int pb = p / 3;
        const int h0 = (u & 31) * 2;

        if (tid == 0) {                              // acquire batch pb
            while (g_bdone[pb] < 64u) __nanosleep(64);
        }
        __syncthreads();
        __threadfence();

        // ---- stage 6 tiles: k = sk*3 + {0:O, 1:I, 2:P}, raw [d][w] ----
        {
            const int dd = tid >> 3;
            const int woff = (tid & 7) * 8;          // halves
#pragma unroll
            for (int k = 0; k < 6; k++) {
                const int sk = k >> 1;               // 0 for k<2? no: use k/3
                const int kk = k;                    // tile index
                const int sl = kk / 3;               // h-slice 0/1
                const int kind = kk % 3;
                const __half* src =
                    (kind == 0) ? g_F2h + (size_t)(2 * p) * SVOL :
                    (kind == 1) ? g_F2h + (size_t)(2 * p + 1) * SVOL :
                                  g_probh + (size_t)p * SVOL;
                cp_async16(Tb + (uint32_t)(kk * 4096 + dd * 64 + woff) * 2,
                           src + (size_t)dd * 4096 + (size_t)(h0 + sl) * 64 + woff);
                (void)sk;
            }
        }
        asm volatile("cp.async.commit_group;");
        asm volatile("cp.async.wait_group 0;");
        __syncthreads();

        // ---- windowed DT from SMEM ----
        const int s = tid >> 8;                      // my h-slice 0/1
        const int t256 = tid & 255;
        const int w2 = (t256 & 31) * 2;
        const int c = (t256 >> 5) * 8;
        const __half* TO = T + (s * 3 + 0) * 4096 + w2;
        const __half* TI = T + (s * 3 + 1) * 4096 + w2;
        const __half* TP = T + (s * 3 + 2) * 4096 + w2;

        float2 ao[8], ai[8];
        dt8v<64, true>(TO, c, ao);
        dt8v<64, true>(TI, c, ai);

        float local = 0.f;
#pragma unroll
        for (int t = 0; t < 8; t++) {
            const float2 pr = __half22float2(
                *reinterpret_cast<const __half2*>(TP + (size_t)(c + t) * 64));
            const float s0 = sqrt_ap(ao[t].x) - sqrt_ap(ai[t].x);
            const float s1 = sqrt_ap(ao[t].y) - sqrt_ap(ai[t].y);
            local = fmaf(s0, pr.x, local);
            local = fmaf(s1, pr.y, local);
        }
#pragma unroll
        for (int o = 16; o > 0; o >>= 1) local += __shfl_down_sync(0xFFFFFFFFu, local, o);
        if ((tid & 31) == 0) red[tid >> 5] = local;
        __syncthreads();
        if (tid == 0) {
            float sum = 0.f;
#pragma unroll
            for (int k = 0; k < 16; k++) sum += red[k];
            atomicAdd(&g_bsum[p], sum);
        }
        __syncthreads();
    }

    // ================= finalization by last-finished block =================
    if (tid == 0) {
        __threadfence();
        sfin = atomicAdd(&g_fin, 1u);
    }
    __syncthreads();
    if (sfin == K12_BLOCKS - 1 && tid < 32) {
        __threadfence();
        float dterm = 0.f;
        if (tid < 16) {
            const float TP_ = g_TP[tid], PS = g_PS[tid], CNT = g_CNT[tid];
            const float FP = PS - TP_;
            const float FN = CNT - TP_;
            dterm = (TP_ + SMOOTHV) / (TP_ + 0.3f * FP + 0.7f * FN + SMOOTHV);
        }
        float bterm = 0.f;
        if (tid < NPAIR) {
            const int bb = tid / 3, cc = tid % 3 + 1;
            const float cnt = g_CNT[bb * 4 + cc];
            if (cnt > 0.f) {
                if (cnt >= (float)SVOL)
                    bterm = -g_PS[bb * 4 + cc] / (float)SVOL;   // sdf == -1 everywhere
                else
                    bterm = g_bsum[tid] / (float)SVOL;
            }
        }
        const float foc = g_focal;
#pragma unroll
        for (int o = 16; o > 0; o >>= 1) {
            dterm += __shfl_down_sync(0xFFFFFFFFu, dterm, o);
            bterm += __shfl_down_sync(0xFFFFFFFFu, bterm, o);
        }
        if (tid == 0) {
            const float l_dice = 1.0f - dterm / 16.0f;
            const float l_main = foc / (float)NTOT;
            const float l_bound = bterm / (12.0f + 1e-8f);
            out[0] = l_dice + l_main + 0.01f * l_bound;
        }
        // reset all state for next graph replay
        if (tid < 16) { g_TP[tid] = 0.f; g_PS[tid] = 0.f; g_CNT[tid] = 0.f; }
        if (tid < NPAIR) g_bsum[tid] = 0.f;
        if (tid < NBATCH) g_bdone[tid] = 0u;
        if (tid == 0) { g_focal = 0.f; g_k12cnt = 0u; g_k3cnt = 0u; g_fin = 0u; }
    }
}

extern "C" void kernel_launch(void* const* d_in, const int* in_sizes, int n_in,
                              void* d_out, int out_size) {
    const float* preds = (const float*)d_in[0];
    const int*   tgt   = (const int*)d_in[1];
    (void)in_sizes; (void)n_in; (void)out_size;

    const int smem = 6 * 4096 * (int)sizeof(__half);   // 48 KB dynamic
    cudaFuncSetAttribute(k_all, cudaFuncAttributeMaxDynamicSharedMemorySize, smem);

    k_all<<<K12_BLOCKS, 512, smem>>>(preds, tgt, (float*)d_out);
}

// round 16
// speedup vs baseline: 1.7407x; 1.1813x over previous
#include <cuda_runtime.h>
#include <cuda_fp16.h>
#include <cstdint>

#define DIMS 64
#define SVOL (64*64*64)
#define NBATCH 4
#define NCLASS 4
#define NPAIR 12
#define NVOL 24
#define NTOT (NBATCH*SVOL)
#define SMOOTHV 1e-5f
#define K12_BLOCKS 256
#define K12_UNITS 256
#define K3_UNITS 384            // 12 pairs * 32 (h-pairs)

__device__ __half g_F2h[(size_t)NVOL * SVOL];    // pass-2 2D SQUARED distances (fp16)
__device__ __half g_probh[(size_t)NPAIR * SVOL]; // probs classes 1..3 (fp16)
__device__ float g_TP[16];      // zero at load; reset by last block each call
__device__ float g_PS[16];
__device__ float g_CNT[16];
__device__ float g_focal;
__device__ float g_bsum[NPAIR];
__device__ volatile unsigned g_bdone[NBATCH];
__device__ unsigned g_k12cnt;
__device__ unsigned g_k3cnt;
__device__ unsigned g_fin;

__device__ __forceinline__ float sqrt_ap(float x) {
    float y; asm("sqrt.approx.f32 %0, %1;" : "=f"(y) : "f"(x)); return y;
}

// nearest set-bit distance within a 64-bit line mask (bit i may be set or not)
__device__ __forceinline__ float ndist(unsigned long long M, int i) {
    if (M == 0ULL) return __int_as_float(0x7f800000);   // +inf
    unsigned long long L = M << (63 - i);
    int dl = L ? __clzll((long long)L) : 9999;
    unsigned long long R = M >> i;
    int dr = R ? (__ffsll((long long)R) - 1) : 9999;
    return (float)min(dl, dr);
}

// ============================================================
// Windowed exact 1D DT over 8 rows x 2 adjacent columns (half2).
// SQ=false: input is distance f; SQ=true: input already squared.
// Results <= 16 provably exact; else exact fp32 full-scan fallback.
// ============================================================
template<int HSTRIDE, bool SQ>
__device__ __forceinline__ void dt8v(const __half* __restrict__ base, int c, float2 acc[8]) {
    const __half2* b2 = reinterpret_cast<const __half2*>(base);
    const int S2 = HSTRIDE / 2;
    const __half2 inf2 = __halves2half2(__ushort_as_half(0x7C00), __ushort_as_half(0x7C00));
    __half2 s[14];
#pragma unroll
    for (int mi = 0; mi < 14; mi++) {
        int j = c - 3 + mi;
        if (j >= 0 && j < 64) {
            __half2 v = b2[(size_t)j * S2];
            s[mi] = SQ ? v : __hmul2(v, v);
        } else s[mi] = inf2;
    }
    const __half2 c1 = __float2half2_rn(1.f);
    const __half2 c4 = __float2half2_rn(4.f);
    const __half2 c9 = __float2half2_rn(9.f);
    __half2 a2[8];
#pragma unroll
    for (int t = 0; t < 8; t++) {
        __half2 a = s[t + 3];
        a = __hmin2(a, __hadd2(s[t + 2], c1)); a = __hmin2(a, __hadd2(s[t + 4], c1));
        a = __hmin2(a, __hadd2(s[t + 1], c4)); a = __hmin2(a, __hadd2(s[t + 5], c4));
        a = __hmin2(a, __hadd2(s[t + 0], c9)); a = __hmin2(a, __hadd2(s[t + 6], c9));
        a2[t] = a;
    }
    __half2 mx2 = a2[0];
#pragma unroll
    for (int t = 1; t < 8; t++) mx2 = __hmax2(mx2, a2[t]);
#pragma unroll
    for (int t = 0; t < 8; t++) acc[t] = __half22float2(a2[t]);
    const float fmx = fmaxf(__low2float(mx2), __high2float(mx2));
    if (__any_sync(0xFFFFFFFFu, fmx > 16.0f)) {
        float jf = 0.f;
        for (int j = 0; j < 64; j++, jf += 1.0f) {
            const float f0 = __half2float(base[(size_t)j * HSTRIDE]);
            const float f1 = __half2float(base[(size_t)j * HSTRIDE + 1]);
            const float q0 = SQ ? f0 : f0 * f0;
            const float q1 = SQ ? f1 : f1 * f1;
#pragma unroll
            for (int t = 0; t < 8; t++) {
                const float dk = (float)(c + t) - jf;
                const float d2 = dk * dk;
                acc[t].x = fminf(acc[t].x, d2 + q0);
                acc[t].y = fminf(acc[t].y, d2 + q1);
            }
        }
    }
}

// ============================================================
// Single persistent kernel, 512 threads, 2 blocks/SM.
// K12 slices and K3 units both work-stolen (batch-major).
// Phase D merged into the post-A barrier; Phase B halved
// (one ndist per position: the trivial direction is 0).
// Last-finished block assembles the loss and resets all state.
// ============================================================
__global__ void __launch_bounds__(512, 2) k_all(const float* __restrict__ preds,
                                                const int* __restrict__ tgt32,
                                                float* __restrict__ out) {
    extern __shared__ __half T[];            // 6 * 4096 halves = 48 KB
    __shared__ unsigned sball[3][64][2];
    __shared__ float red13[12 * 16];
    __shared__ float red[16];
    __shared__ int sany;
    __shared__ unsigned su;
    __shared__ unsigned sfin;
    const int tid = threadIdx.x;
    const unsigned full = 0xFFFFFFFFu;
    const int wid = tid >> 5;

    // ---------- int64 detection: warp 0 checks 64 odd words ----------
    if (tid < 32) {
        const int v = tgt32[2 * tid + 1] | tgt32[2 * (tid + 32) + 1];
        const unsigned bal = __ballot_sync(full, v != 0);
        if (tid == 0) sany = (int)bal;
    }
    __syncthreads();
    const int f64 = (sany == 0) ? 1 : 0;

    // ================= K12: work-stolen slices =================
    for (;;) {
        if (tid == 0) su = atomicAdd(&g_k12cnt, 1u);
        __syncthreads();                      // su visible; sball/red13/T reuse safe
        const unsigned u12 = su;
        if (u12 >= K12_UNITS) break;
        const int b = (int)(u12 >> 6);
        const int d = (int)(u12 & 63);

        float a9[9];
#pragma unroll
        for (int q = 0; q < 9; q++) a9[q] = 0.f;
        int cn1 = 0, cn2 = 0, cn3 = 0;

        // ---------- Phase A ----------
#pragma unroll
        for (int r = 0; r < 8; r++) {
            const int sl = tid + r * 512;
            const int s = d * 4096 + sl;
            const int gidx = b * SVOL + s;
            const int t = tgt32[f64 ? (gidx << 1) : gidx];

            const float x0 = preds[(size_t)(b * 4 + 0) * SVOL + s];
            const float x1 = preds[(size_t)(b * 4 + 1) * SVOL + s];
            const float x2 = preds[(size_t)(b * 4 + 2) * SVOL + s];
            const float x3 = preds[(size_t)(b * 4 + 3) * SVOL + s];

            const float m  = fmaxf(fmaxf(x0, x1), fmaxf(x2, x3));
            const float e0 = __expf(x0 - m), e1 = __expf(x1 - m);
            const float e2 = __expf(x2 - m), e3 = __expf(x3 - m);
            const float se = e0 + e1 + e2 + e3;
            const float inv = __fdividef(1.0f, se);
            const float p0 = e0 * inv, p1 = e1 * inv, p2 = e2 * inv, p3 = e3 * inv;

            const float xt = (t == 0) ? x0 : (t == 1) ? x1 : (t == 2) ? x2 : x3;
            const float ce = -(xt - m - __logf(se));
            const float pt = (t == 0) ? p0 : (t == 1) ? p1 : (t == 2) ? p2 : p3;
            const float om = 1.0f - pt;

            g_probh[(size_t)(b * 3 + 0) * SVOL + s] = __float2half(p1);
            g_probh[(size_t)(b * 3 + 1) * SVOL + s] = __float2half(p2);
            g_probh[(size_t)(b * 3 + 2) * SVOL + s] = __float2half(p3);

            a9[0] += (t == 0) ? p0 : 0.f;
            a9[1] += (t == 1) ? p1 : 0.f;
            a9[2] += (t == 2) ? p2 : 0.f;
            a9[3] += (t == 3) ? p3 : 0.f;
            a9[4] += p0; a9[5] += p1; a9[6] += p2; a9[7] += p3;
            a9[8] += om * om * ce;

            const unsigned bal1 = __ballot_sync(full, t == 1);
            const unsigned bal2 = __ballot_sync(full, t == 2);
            const unsigned bal3 = __ballot_sync(full, t == 3);
            cn1 += __popc(bal1); cn2 += __popc(bal2); cn3 += __popc(bal3);
            if ((tid & 31) == 0) {
                const int h = r * 8 + (wid >> 1);
                const int hf = wid & 1;
                sball[0][h][hf] = bal1;
                sball[1][h][hf] = bal2;
                sball[2][h][hf] = bal3;
            }
        }

        // ---------- Phase D part 1: warp-level reduce (pre-barrier) ----------
#pragma unroll
        for (int q = 0; q < 9; q++) {
            float v = a9[q];
#pragma unroll
            for (int o = 16; o > 0; o >>= 1) v += __shfl_down_sync(full, v, o);
            if ((tid & 31) == 0) red13[q * 16 + wid] = v;
        }
        if ((tid & 31) == 0) {
            red13[9 * 16 + wid]  = (float)cn1;
            red13[10 * 16 + wid] = (float)cn2;
            red13[11 * 16 + wid] = (float)cn3;
        }
        __syncthreads();                      // covers sball + red13

        // ---------- Phase D part 2: atomics (concurrent with Phase B) ----------
        if (tid < 12) {
            float sum = 0.f;
#pragma unroll
            for (int k = 0; k < 16; k++) sum += red13[tid * 16 + k];
            if (tid < 4)       atomicAdd(&g_TP[b * 4 + tid], sum);
            else if (tid < 8)  atomicAdd(&g_PS[b * 4 + tid - 4], sum);
            else if (tid == 8) atomicAdd(&g_focal, sum);
            else {
                atomicAdd(&g_CNT[b * 4 + tid - 8], sum);
                atomicAdd(&g_CNT[b * 4], -sum);     // CNT0 = 4096 - c1 - c2 - c3
            }
        }
        if (tid == 12) atomicAdd(&g_CNT[b * 4], 4096.0f);

        // ---------- Phase B: pass-1 line distances (halved) ----------
        {
            const int h = tid >> 3;
            const int w0 = (tid & 7) * 8;
#pragma unroll
            for (int cm = 0; cm < 3; cm++) {
                const unsigned long long M = (unsigned long long)sball[cm][h][0] |
                                             ((unsigned long long)sball[cm][h][1] << 32);
                __half* t0 = T + (cm * 2 + 0) * 4096 + h * 64;
                __half* t1 = T + (cm * 2 + 1) * 4096 + h * 64;
#pragma unroll
                for (int q = 0; q < 8; q++) {
                    const int w = w0 + q;
                    const bool st = (M >> w) & 1ULL;
                    const unsigned long long X = st ? ~M : M;
                    const float dd = ndist(X, w);
                    t0[w] = __float2half(st ? 0.f : dd);
                    t1[w] = __float2half(st ? dd : 0.f);
                }
            }
        }
        __syncthreads();

        // ---------- Phase C: H-pass, SMEM -> g_F2h (store d^2) ----------
        {
            const int w2 = (tid & 31) * 2;
            const int c = ((tid >> 5) & 7) * 8;
            const int vh = tid >> 8;             // 0..1
#pragma unroll
            for (int vi = 0; vi < 3; vi++) {
                const int vol = vh * 3 + vi;
                const __half* base = T + vol * 4096 + w2;
                float2 acc[8];
                dt8v<64, false>(base, c, acc);
                __half* dst = g_F2h + (size_t)(b * 6 + vol) * SVOL + (size_t)d * 4096 +
                              (size_t)c * 64 + w2;
#pragma unroll
                for (int t = 0; t < 8; t++) {
                    __half2 o = __halves2half2(__float2half(acc[t].x),
                                               __float2half(acc[t].y));
                    *reinterpret_cast<__half2*>(dst + (size_t)t * 64) = o;
                }
            }
        }

        // ---- release this slice ----
        __threadfence();
        __syncthreads();
        if (tid == 0) atomicAdd((unsigned*)&g_bdone[b], 1u);
    }

    // ================= K3: work-stolen D-pass units (direct global) =================
    for (;;) {
        if (tid == 0) su = atomicAdd(&g_k3cnt, 1u);
        __syncthreads();
        const unsigned u = su;
        if (u >= K3_UNITS) break;
        const int p = u >> 5;                        // 0..11 (batch-major)
        const int pb = p / 3;
        const int h = (u & 31) * 2 + (tid >> 8);     // 2 h-slices per block
        const int t256 = tid & 255;
        const int w2 = (t256 & 31) * 2;
        const int c = (t256 >> 5) * 8;

        if (tid == 0) {                              // acquire batch pb
            while (g_bdone[pb] < 64u) __nanosleep(64);
        }
        __syncthreads();
        __threadfence();

        const __half* baseO = g_F2h + (size_t)(2 * p) * SVOL + (size_t)h * 64 + w2;
        const __half* baseI = baseO + SVOL;

        float2 ao[8], ai[8];
        dt8v<4096, true>(baseO, c, ao);
        dt8v<4096, true>(baseI, c, ai);

        const __half* pp = g_probh + (size_t)p * SVOL + (size_t)c * 4096 + (size_t)h * 64 + w2;
        float local = 0.f;
#pragma unroll
        for (int t = 0; t < 8; t++) {
            const float2 pr = __half22float2(*reinterpret_cast<const __half2*>(pp + (size_t)t * 4096));
            const float s0 = sqrt_ap(ao[t].x) - sqrt_ap(ai[t].x);
            const float s1 = sqrt_ap(ao[t].y) - sqrt_ap(ai[t].y);
            local = fmaf(s0, pr.x, local);
            local = fmaf(s1, pr.y, local);
        }
#pragma unroll
        for (int o = 16; o > 0; o >>= 1) local += __shfl_down_sync(0xFFFFFFFFu, local, o);
        if ((tid & 31) == 0) red[tid >> 5] = local;
        __syncthreads();
        if (tid == 0) {
            float sum = 0.f;
#pragma unroll
            for (int k = 0; k < 16; k++) sum += red[k];
            atomicAdd(&g_bsum[p], sum);
        }
        __syncthreads();
    }

    // ================= finalization by last-finished block =================
    if (tid == 0) {
        __threadfence();
        sfin = atomicAdd(&g_fin, 1u);
    }
    __syncthreads();
    if (sfin == K12_BLOCKS - 1 && tid < 32) {
        __threadfence();
        float dterm = 0.f;
        if (tid < 16) {
            const float TP_ = g_TP[tid], PS = g_PS[tid], CNT = g_CNT[tid];
            const float FP = PS - TP_;
            const float FN = CNT - TP_;
            dterm = (TP_ + SMOOTHV) / (TP_ + 0.3f * FP + 0.7f * FN + SMOOTHV);
        }
        float bterm = 0.f;
        if (tid < NPAIR) {
            const int bb = tid / 3, cc = tid % 3 + 1;
            const float cnt = g_CNT[bb * 4 + cc];
            if (cnt > 0.f) {
                if (cnt >= (float)SVOL)
                    bterm = -g_PS[bb * 4 + cc] / (float)SVOL;   // sdf == -1 everywhere
                else
                    bterm = g_bsum[tid] / (float)SVOL;
            }
        }
        const float foc = g_focal;
#pragma unroll
        for (int o = 16; o > 0; o >>= 1) {
            dterm += __shfl_down_sync(0xFFFFFFFFu, dterm, o);
            bterm += __shfl_down_sync(0xFFFFFFFFu, bterm, o);
        }
        if (tid == 0) {
            const float l_dice = 1.0f - dterm / 16.0f;
            const float l_main = foc / (float)NTOT;
            const float l_bound = bterm / (12.0f + 1e-8f);
            out[0] = l_dice + l_main + 0.01f * l_bound;
        }
        // reset all state for next graph replay
        if (tid < 16) { g_TP[tid] = 0.f; g_PS[tid] = 0.f; g_CNT[tid] = 0.f; }
        if (tid < NPAIR) g_bsum[tid] = 0.f;
        if (tid < NBATCH) g_bdone[tid] = 0u;
        if (tid == 0) { g_focal = 0.f; g_k12cnt = 0u; g_k3cnt = 0u; g_fin = 0u; }
    }
}

extern "C" void kernel_launch(void* const* d_in, const int* in_sizes, int n_in,
                              void* d_out, int out_size) {
    const float* preds = (const float*)d_in[0];
    const int*   tgt   = (const int*)d_in[1];
    (void)in_sizes; (void)n_in; (void)out_size;

    const int smem = 6 * 4096 * (int)sizeof(__half);   // 48 KB dynamic
    cudaFuncSetAttribute(k_all, cudaFuncAttributeMaxDynamicSharedMemorySize, smem);

    k_all<<<K12_BLOCKS, 512, smem>>>(preds, tgt, (float*)d_out);
}